// round 3
// baseline (speedup 1.0000x reference)
#include <cuda_runtime.h>

// B3-spline UWT (à trous), J=3, fused single kernel.
// x (8,1024,1024) f32 -> out (8,4,1024,1024) = [w1,w2,w3,c3]
// One CTA = 64x64 output tile, 96-row working grid, pitch 100 (bank decorrelation
// + padding absorbs unaligned tap windows). Interior tiles read x straight from
// global (no c0 staging). 2 smem planes (A = coeff, Y = H-conv temp) = 75 KB,
// 3 CTAs/SM. Emits fused into W-conv passes; c_j written in place over c_{j-1}.

namespace {

constexpr int HW   = 1024;
constexpr int Sg   = 96;    // working grid rows/cols
constexpr int PIT  = 100;   // smem pitch (floats)
constexpr int CEN  = 16;
constexpr int TILE = 64;
constexpr int NT   = 256;
constexpr float W0 = 0.0625f, W1 = 0.25f, W2 = 0.375f;

__device__ __forceinline__ int refl(int i) {
    if (i < 0) i = -i;
    if (i >= HW) i = 2 * HW - 2 - i;
    return i;
}

// Vertical 5-tap conv, dilation D. Item: RPB rows x 2 cols (float2),
// streaming RPB+4D source rows. SPIT = source pitch (global or smem).
template <int D, int RPB, int SPIT>
__device__ __forceinline__ void hconv(const float* __restrict__ src,
                                      float* __restrict__ dst,
                                      int r0, int nrb, int c0, int ncp, int tid) {
    const int items = nrb * ncp;
    for (int it = tid; it < items; it += NT) {
        const int c  = c0 + 2 * (it % ncp);
        const int y0 = r0 + (it / ncp) * RPB;
        const float* sp = src + (y0 - 2 * D) * SPIT + c;
        float2 acc[RPB];
#pragma unroll
        for (int i = 0; i < RPB; ++i) acc[i] = make_float2(0.f, 0.f);
#pragma unroll
        for (int rr = 0; rr < RPB + 4 * D; ++rr) {
            const float2 v = *reinterpret_cast<const float2*>(sp + rr * SPIT);
#pragma unroll
            for (int i = 0; i < RPB; ++i) {
                const int t = rr - i;
                if (t >= 0 && t <= 4 * D && (t % D) == 0) {
                    const float w = (t == 0 || t == 4 * D) ? W0
                                  : (t == D || t == 3 * D) ? W1 : W2;
                    acc[i].x += w * v.x; acc[i].y += w * v.y;
                }
            }
        }
        float* dp = dst + y0 * PIT + c;
#pragma unroll
        for (int i = 0; i < RPB; ++i)
            *reinterpret_cast<float2*>(dp + i * PIT) = acc[i];
    }
}

// Horizontal 5-tap conv, dilation D. Item: 1 row x 16 cols.
// Aligned float4 window loads (spill into row padding is harmless: garbage only
// reaches columns outside the level's validity cone, which are never consumed).
// Center items emit w = prev - c (+ optionally c) to global; STOREC writes c_j
// into A in place (item-local read-before-write, items own disjoint cells).
template <int D, bool STOREC, bool EMITC, bool PREVG>
__device__ __forceinline__ void wconv(const float* __restrict__ Ybuf,
                                      float* Abuf,
                                      int r0, int nrows, int cg0, int ncg,
                                      const float* __restrict__ prevG,
                                      float* __restrict__ owp,
                                      float* __restrict__ ocp,
                                      int ty0, int tx0, int tid) {
    constexpr int LOFF = (D == 1) ? 4 : 2 * D;          // floats before x16 (aligned)
    constexpr int NLD  = (16 + LOFF + 2 * D + 3) / 4;   // float4 loads
    constexpr int B0   = LOFF - 2 * D;                  // buf index of x16-2D
    const int items = nrows * ncg;
    for (int it = tid; it < items; it += NT) {
        const int cg  = cg0 + (it % ncg);
        const int y   = r0 + it / ncg;
        const int x16 = cg * 16;
        const float* row = Ybuf + y * PIT + x16 - LOFF;
        float buf[NLD * 4];
#pragma unroll
        for (int j = 0; j < NLD; ++j) {
            const float4 v = *reinterpret_cast<const float4*>(row + 4 * j);
            buf[4 * j] = v.x; buf[4 * j + 1] = v.y;
            buf[4 * j + 2] = v.z; buf[4 * j + 3] = v.w;
        }
        float o[16];
#pragma unroll
        for (int i = 0; i < 16; ++i)
            o[i] = W0 * (buf[B0 + i] + buf[B0 + i + 4 * D]) +
                   W1 * (buf[B0 + i + D] + buf[B0 + i + 3 * D]) +
                   W2 * buf[B0 + i + 2 * D];

        const bool cen = (y >= CEN) & (y < CEN + TILE) &
                         (x16 >= CEN) & (x16 < CEN + TILE);
        if (cen) {
            const size_t go = (size_t)(ty0 + y - CEN) * HW + (tx0 + x16 - CEN);
            const float* pp = PREVG ? (prevG + go) : (Abuf + y * PIT + x16);
#pragma unroll
            for (int q = 0; q < 4; ++q) {
                const float4 p4 = *reinterpret_cast<const float4*>(pp + 4 * q);
                *reinterpret_cast<float4*>(owp + go + 4 * q) =
                    make_float4(p4.x - o[4 * q],     p4.y - o[4 * q + 1],
                                p4.z - o[4 * q + 2], p4.w - o[4 * q + 3]);
                if (EMITC)
                    *reinterpret_cast<float4*>(ocp + go + 4 * q) =
                        make_float4(o[4 * q],     o[4 * q + 1],
                                    o[4 * q + 2], o[4 * q + 3]);
            }
        }
        if (STOREC) {
            float* dp = Abuf + y * PIT + x16;
#pragma unroll
            for (int q = 0; q < 4; ++q)
                *reinterpret_cast<float4*>(dp + 4 * q) =
                    make_float4(o[4 * q],     o[4 * q + 1],
                                o[4 * q + 2], o[4 * q + 3]);
        }
    }
}

}  // namespace

extern __shared__ float g_smem[];

__global__ void __launch_bounds__(NT, 3)
uwt_kernel(const float* __restrict__ x, float* __restrict__ out) {
    float* A = g_smem;              // coeff plane c_j (in-place per level)
    float* Y = g_smem + Sg * PIT;   // H-conv temp

    const int tid = threadIdx.x;
    const int tx0 = (blockIdx.x & 15) * TILE;
    const int ty0 = (blockIdx.x >> 4) * TILE;
    const float* xb = x + (size_t)blockIdx.y * HW * HW;
    float* ob = out + (size_t)blockIdx.y * 4 * HW * HW;

    const bool interior = (tx0 > 0) & (tx0 < HW - TILE) & (ty0 > 0) & (ty0 < HW - TILE);

    // Level 1 H-conv (d=1): rows 4..91, all 48 col pairs.
    if (interior) {
        // Read x directly from global; no staging.
        const float* src = xb + (size_t)(ty0 - CEN) * HW + (tx0 - CEN);
        hconv<1, 8, HW>(src, Y, 4, 11, 0, 48, tid);
    } else {
        // Edge tile: stage reflected c0 into A, conv from smem.
        for (int i = tid; i < Sg * Sg; i += NT) {
            const int y = i / Sg, xx = i - y * Sg;
            A[y * PIT + xx] =
                xb[(size_t)refl(ty0 - CEN + y) * HW + refl(tx0 - CEN + xx)];
        }
        __syncthreads();
        hconv<1, 8, PIT>(A, Y, 4, 11, 0, 48, tid);
    }
    __syncthreads();
    // W-conv 1: c1 -> A (valid cols 2..93); emit w1 = c0(global) - c1.
    wconv<1, true, false, true>(Y, A, 4, 88, 0, 6, xb, ob, nullptr, ty0, tx0, tid);
    __syncthreads();

    // Level 2 (d=2): rows 8..87, col pairs 4..91.
    hconv<2, 16, PIT>(A, Y, 8, 5, 4, 44, tid);
    __syncthreads();
    wconv<2, true, false, false>(Y, A, 8, 80, 0, 6, nullptr,
                                 ob + (size_t)HW * HW, nullptr, ty0, tx0, tid);
    __syncthreads();

    // Level 3 (d=4): rows 16..79, col pairs 8..87; emit w3 + c3, no smem store.
    hconv<4, 16, PIT>(A, Y, 16, 4, 8, 40, tid);
    __syncthreads();
    wconv<4, false, true, false>(Y, A, 16, 64, 1, 4, nullptr,
                                 ob + 2 * (size_t)HW * HW,
                                 ob + 3 * (size_t)HW * HW, ty0, tx0, tid);
}

extern "C" void kernel_launch(void* const* d_in, const int* in_sizes, int n_in,
                              void* d_out, int out_size) {
    const float* x = (const float*)d_in[0];
    float* out = (float*)d_out;
    const int smemBytes = 2 * Sg * PIT * (int)sizeof(float);  // 76800 B
    cudaFuncSetAttribute(uwt_kernel, cudaFuncAttributeMaxDynamicSharedMemorySize,
                         smemBytes);
    dim3 grid(256, 8);
    uwt_kernel<<<grid, NT, smemBytes>>>(x, out);
}

// round 4
// speedup vs baseline: 1.1766x; 1.1766x over previous
#include <cuda_runtime.h>

// B3-spline UWT (à trous), J=3, fused single kernel.
// x (8,1024,1024) f32 -> out (8,4,1024,1024) = [w1,w2,w3,c3]
//
// One CTA = 64x64 output tile, 96x96 working grid, PIT=96 (72 KB, 3 CTAs/SM).
// Conflict-free smem rule: every access is float2-per-lane with lanes
// contiguous, so each 16-lane LDS.64 phase covers one contiguous 128B run.
// Emits fused into W-conv passes; c_j overwrites c_{j-1} in place.

namespace {

constexpr int HW   = 1024;
constexpr int Sg   = 96;
constexpr int PIT  = 96;
constexpr int CEN  = 16;
constexpr int TILE = 64;
constexpr int NT   = 256;
constexpr float W0 = 0.0625f, W1 = 0.25f, W2 = 0.375f;

__device__ __forceinline__ int refl(int i) {
    if (i < 0) i = -i;
    if (i >= HW) i = 2 * HW - 2 - i;
    return i;
}

__device__ __forceinline__ float2 ld2(const float* p) {
    return *reinterpret_cast<const float2*>(p);
}

// Vertical 5-tap conv, dilation D. Item: RPB rows x 2 cols (float2),
// streaming RPB+4D source rows. Lanes contiguous in a row -> conflict-free.
template <int D, int RPB, int SPIT>
__device__ __forceinline__ void hconv(const float* __restrict__ src,
                                      float* __restrict__ dst,
                                      int r0, int nrb, int c0, int ncp, int tid) {
    const int items = nrb * ncp;
    for (int it = tid; it < items; it += NT) {
        const int c  = c0 + 2 * (it % ncp);
        const int y0 = r0 + (it / ncp) * RPB;
        const float* sp = src + (y0 - 2 * D) * SPIT + c;
        float2 acc[RPB];
#pragma unroll
        for (int i = 0; i < RPB; ++i) acc[i] = make_float2(0.f, 0.f);
#pragma unroll
        for (int rr = 0; rr < RPB + 4 * D; ++rr) {
            const float2 v = ld2(sp + rr * SPIT);
#pragma unroll
            for (int i = 0; i < RPB; ++i) {
                const int t = rr - i;
                if (t >= 0 && t <= 4 * D && (t % D) == 0) {
                    const float w = (t == 0 || t == 4 * D) ? W0
                                  : (t == D || t == 3 * D) ? W1 : W2;
                    acc[i].x += w * v.x; acc[i].y += w * v.y;
                }
            }
        }
        float* dp = dst + y0 * PIT + c;
#pragma unroll
        for (int i = 0; i < RPB; ++i)
            *reinterpret_cast<float2*>(dp + i * PIT) = acc[i];
    }
}

// Horizontal 5-tap conv, dilation D. Item: 1 row x 2 cols (one lane).
// D=1: 3 aligned float2 loads; D even: 5 aligned float2 loads. All phases
// contiguous -> conflict-free. Center items emit w = prev - c (+ optionally c);
// STOREC writes c_j into A in place (item-local read-before-write).
template <int D, bool STOREC, bool EMITC, bool PREVG>
__device__ __forceinline__ void wconv(const float* __restrict__ Ybuf,
                                      float* Abuf,
                                      int r0, int nrows, int cp0, int ncp,
                                      const float* __restrict__ prevG,
                                      float* __restrict__ owp,
                                      float* __restrict__ ocp,
                                      int ty0, int tx0, int tid) {
    const int items = nrows * ncp;
    for (int it = tid; it < items; it += NT) {
        const int p  = cp0 + it % ncp;
        const int y  = r0 + it / ncp;
        const int x2 = p * 2;
        const float* row = Ybuf + y * PIT + x2;
        float o0, o1;
        if (D == 1) {
            const float2 a = ld2(row - 2), b = ld2(row), c = ld2(row + 2);
            o0 = W0 * (a.x + c.x) + W1 * (a.y + b.y) + W2 * b.x;
            o1 = W0 * (a.y + c.y) + W1 * (b.x + c.x) + W2 * b.y;
        } else {
            const float2 m2 = ld2(row - 2 * D), m1 = ld2(row - D), z = ld2(row),
                         p1 = ld2(row + D), p2 = ld2(row + 2 * D);
            o0 = W0 * (m2.x + p2.x) + W1 * (m1.x + p1.x) + W2 * z.x;
            o1 = W0 * (m2.y + p2.y) + W1 * (m1.y + p1.y) + W2 * z.y;
        }
        const bool cen = (y >= CEN) & (y < CEN + TILE) &
                         (x2 >= CEN) & (x2 < CEN + TILE);
        if (cen) {
            const size_t go = (size_t)(ty0 + y - CEN) * HW + (tx0 + x2 - CEN);
            float2 pv;
            if (PREVG) pv = ld2(prevG + go);
            else       pv = ld2(Abuf + y * PIT + x2);
            *reinterpret_cast<float2*>(owp + go) =
                make_float2(pv.x - o0, pv.y - o1);
            if (EMITC)
                *reinterpret_cast<float2*>(ocp + go) = make_float2(o0, o1);
        }
        if (STOREC)
            *reinterpret_cast<float2*>(Abuf + y * PIT + x2) = make_float2(o0, o1);
    }
}

}  // namespace

extern __shared__ float g_smem[];

__global__ void __launch_bounds__(NT, 3)
uwt_kernel(const float* __restrict__ x, float* __restrict__ out) {
    float* A = g_smem;              // coeff plane c_j (in-place per level)
    float* Y = g_smem + Sg * PIT;   // H-conv temp

    const int tid = threadIdx.x;
    const int tx0 = (blockIdx.x & 15) * TILE;
    const int ty0 = (blockIdx.x >> 4) * TILE;
    const float* xb = x + (size_t)blockIdx.y * HW * HW;
    float* ob = out + (size_t)blockIdx.y * 4 * HW * HW;

    const bool interior = (tx0 > 0) & (tx0 < HW - TILE) &
                          (ty0 > 0) & (ty0 < HW - TILE);

    // Level 1 H-conv (d=1): out rows 4..91, cols 0..95.
    if (interior) {
        const float* src = xb + (size_t)(ty0 - CEN) * HW + (tx0 - CEN);
        hconv<1, 8, HW>(src, Y, 4, 11, 0, 48, tid);
    } else {
        for (int i = tid; i < Sg * Sg; i += NT) {
            const int y = i / Sg, xx = i - y * Sg;
            A[y * PIT + xx] =
                xb[(size_t)refl(ty0 - CEN + y) * HW + refl(tx0 - CEN + xx)];
        }
        __syncthreads();
        hconv<1, 8, PIT>(A, Y, 4, 11, 0, 48, tid);
    }
    __syncthreads();

    // W-conv 1: c1 -> A on rows 4..91 x cols 4..91; emit w1 = c0 - c1.
    if (interior)
        wconv<1, true, false, true>(Y, A, 4, 88, 2, 44, xb, ob, nullptr,
                                    ty0, tx0, tid);
    else
        wconv<1, true, false, false>(Y, A, 4, 88, 2, 44, nullptr, ob, nullptr,
                                     ty0, tx0, tid);
    __syncthreads();

    // Level 2 (d=2): h2 out rows 8..87 x cols 4..91.
    hconv<2, 16, PIT>(A, Y, 8, 5, 4, 44, tid);
    __syncthreads();
    // w2: c2 -> A on rows 8..87 x cols 8..87; emit w2 = c1 - c2.
    wconv<2, true, false, false>(Y, A, 8, 80, 4, 40, nullptr,
                                 ob + (size_t)HW * HW, nullptr, ty0, tx0, tid);
    __syncthreads();

    // Level 3 (d=4): h3 out rows 16..79 x cols 8..87.
    hconv<4, 16, PIT>(A, Y, 16, 4, 8, 40, tid);
    __syncthreads();
    // w3: center only; emit w3 = c2 - c3 and c3. No smem store.
    wconv<4, false, true, false>(Y, A, 16, 64, 8, 32, nullptr,
                                 ob + 2 * (size_t)HW * HW,
                                 ob + 3 * (size_t)HW * HW, ty0, tx0, tid);
}

extern "C" void kernel_launch(void* const* d_in, const int* in_sizes, int n_in,
                              void* d_out, int out_size) {
    const float* x = (const float*)d_in[0];
    float* out = (float*)d_out;
    const int smemBytes = 2 * Sg * PIT * (int)sizeof(float);  // 73728 B
    cudaFuncSetAttribute(uwt_kernel, cudaFuncAttributeMaxDynamicSharedMemorySize,
                         smemBytes);
    dim3 grid(256, 8);
    uwt_kernel<<<grid, NT, smemBytes>>>(x, out);
}

// round 5
// speedup vs baseline: 1.2746x; 1.0832x over previous
#include <cuda_runtime.h>

// B3-spline UWT (à trous), J=3, fused single kernel.
// x (8,1024,1024) f32 -> out (8,4,1024,1024) = [w1,w2,w3,c3]
//
// One CTA = 64x64 output tile, 96x96 working grid, PIT=96 (72 KB, 3 CTAs/SM).
// Conflict-free smem rule: lanes contiguous, lane stride == access width, so
// every LDS/STS phase covers one contiguous 128B run. wconv uses float4 items
// (4 outputs/lane); hconv streams rows with register accumulators.
// Emits fused into W-conv passes; c_j overwrites c_{j-1} in place.

namespace {

constexpr int HW   = 1024;
constexpr int Sg   = 96;
constexpr int PIT  = 96;
constexpr int CEN  = 16;
constexpr int TILE = 64;
constexpr int NT   = 256;
constexpr float W0 = 0.0625f, W1 = 0.25f, W2 = 0.375f;

__device__ __forceinline__ int refl(int i) {
    if (i < 0) i = -i;
    if (i >= HW) i = 2 * HW - 2 - i;
    return i;
}

__device__ __forceinline__ float2 ld2(const float* p) {
    return *reinterpret_cast<const float2*>(p);
}
__device__ __forceinline__ float4 ld4(const float* p) {
    return *reinterpret_cast<const float4*>(p);
}

// Vertical 5-tap conv, dilation D, float2 lanes (W=2), RPB rows per item.
template <int D, int RPB, int SPIT, int NCP>
__device__ __forceinline__ void hconv2(const float* __restrict__ src,
                                       float* __restrict__ dst,
                                       int r0, int nrb, int c0, int tid) {
    const int items = nrb * NCP;
    for (int it = tid; it < items; it += NT) {
        const int c  = c0 + 2 * (it % NCP);
        const int y0 = r0 + (it / NCP) * RPB;
        const float* sp = src + (y0 - 2 * D) * SPIT + c;
        float2 acc[RPB];
#pragma unroll
        for (int i = 0; i < RPB; ++i) acc[i] = make_float2(0.f, 0.f);
#pragma unroll
        for (int rr = 0; rr < RPB + 4 * D; ++rr) {
            const float2 v = ld2(sp + rr * SPIT);
#pragma unroll
            for (int i = 0; i < RPB; ++i) {
                const int t = rr - i;
                if (t >= 0 && t <= 4 * D && (t % D) == 0) {
                    const float w = (t == 0 || t == 4 * D) ? W0
                                  : (t == D || t == 3 * D) ? W1 : W2;
                    acc[i].x += w * v.x; acc[i].y += w * v.y;
                }
            }
        }
        float* dp = dst + y0 * PIT + c;
#pragma unroll
        for (int i = 0; i < RPB; ++i)
            *reinterpret_cast<float2*>(dp + i * PIT) = acc[i];
    }
}

// Vertical 5-tap conv, dilation 1, float4 lanes, RPB=8 (level-1 front end).
template <int SPIT, int NCG>
__device__ __forceinline__ void hconv4_d1(const float* __restrict__ src,
                                          float* __restrict__ dst,
                                          int r0, int nrb, int tid) {
    constexpr int RPB = 8;
    const int items = nrb * NCG;
    for (int it = tid; it < items; it += NT) {
        const int c  = 4 * (it % NCG);
        const int y0 = r0 + (it / NCG) * RPB;
        const float* sp = src + (y0 - 2) * SPIT + c;
        float4 acc[RPB];
#pragma unroll
        for (int i = 0; i < RPB; ++i) acc[i] = make_float4(0.f, 0.f, 0.f, 0.f);
#pragma unroll
        for (int rr = 0; rr < RPB + 4; ++rr) {
            const float4 v = ld4(sp + rr * SPIT);
#pragma unroll
            for (int i = 0; i < RPB; ++i) {
                const int t = rr - i;
                if (t >= 0 && t <= 4) {
                    const float w = (t == 0 || t == 4) ? W0 : (t == 2 ? W2 : W1);
                    acc[i].x += w * v.x; acc[i].y += w * v.y;
                    acc[i].z += w * v.z; acc[i].w += w * v.w;
                }
            }
        }
        float* dp = dst + y0 * PIT + c;
#pragma unroll
        for (int i = 0; i < RPB; ++i)
            *reinterpret_cast<float4*>(dp + i * PIT) = acc[i];
    }
}

// Horizontal 5-tap conv, dilation D, float4 items (4 outputs per lane).
// Aligned float4 window loads; lanes contiguous -> conflict-free.
// Center items emit w = prev - c (+ optionally c) to global as float4.
template <int D, bool STOREC, bool EMITC, bool PREVG, int NCG>
__device__ __forceinline__ void wconv(const float* __restrict__ Ybuf,
                                      float* Abuf,
                                      int r0, int nrows, int cg0,
                                      const float* __restrict__ prevG,
                                      float* __restrict__ owp,
                                      float* __restrict__ ocp,
                                      int ty0, int tx0, int tid) {
    constexpr int LOFF = (D == 4) ? 8 : 4;            // floats before x (aligned)
    constexpr int NLD  = (LOFF + 4 + 2 * D + 3) / 4;  // float4 loads
    constexpr int B0   = LOFF - 2 * D;                // buf idx of x-2D
    const int items = nrows * NCG;
    for (int it = tid; it < items; it += NT) {
        const int x  = (cg0 + it % NCG) * 4;
        const int y  = r0 + it / NCG;
        const float* row = Ybuf + y * PIT + x - LOFF;
        float buf[NLD * 4];
#pragma unroll
        for (int j = 0; j < NLD; ++j) {
            const float4 v = ld4(row + 4 * j);
            buf[4 * j] = v.x; buf[4 * j + 1] = v.y;
            buf[4 * j + 2] = v.z; buf[4 * j + 3] = v.w;
        }
        float o[4];
#pragma unroll
        for (int i = 0; i < 4; ++i)
            o[i] = W0 * (buf[B0 + i] + buf[B0 + i + 4 * D]) +
                   W1 * (buf[B0 + i + D] + buf[B0 + i + 3 * D]) +
                   W2 * buf[B0 + i + 2 * D];

        const bool cen = (y >= CEN) & (y < CEN + TILE) &
                         (x >= CEN) & (x < CEN + TILE);
        if (cen) {
            const size_t go = (size_t)(ty0 + y - CEN) * HW + (tx0 + x - CEN);
            float4 pv;
            if (PREVG) pv = ld4(prevG + go);
            else       pv = ld4(Abuf + y * PIT + x);
            *reinterpret_cast<float4*>(owp + go) =
                make_float4(pv.x - o[0], pv.y - o[1], pv.z - o[2], pv.w - o[3]);
            if (EMITC)
                *reinterpret_cast<float4*>(ocp + go) =
                    make_float4(o[0], o[1], o[2], o[3]);
        }
        if (STOREC)
            *reinterpret_cast<float4*>(Abuf + y * PIT + x) =
                make_float4(o[0], o[1], o[2], o[3]);
    }
}

}  // namespace

extern __shared__ float g_smem[];

__global__ void __launch_bounds__(NT, 3)
uwt_kernel(const float* __restrict__ x, float* __restrict__ out) {
    float* A = g_smem;              // coeff plane c_j (in-place per level)
    float* Y = g_smem + Sg * PIT;   // H-conv temp

    const int tid = threadIdx.x;
    const int tx0 = (blockIdx.x & 15) * TILE;
    const int ty0 = (blockIdx.x >> 4) * TILE;
    const float* xb = x + (size_t)blockIdx.y * HW * HW;
    float* ob = out + (size_t)blockIdx.y * 4 * HW * HW;

    const bool interior = (tx0 > 0) & (tx0 < HW - TILE) &
                          (ty0 > 0) & (ty0 < HW - TILE);

    // Level 1 H-conv (d=1): out rows 4..91 x cols 0..95.
    if (interior) {
        const float* src = xb + (size_t)(ty0 - CEN) * HW + (tx0 - CEN);
        hconv4_d1<HW, 24>(src, Y, 4, 11, tid);
    } else {
        for (int i = tid; i < Sg * Sg; i += NT) {
            const int y = i / Sg, xx = i - y * Sg;
            A[y * PIT + xx] =
                xb[(size_t)refl(ty0 - CEN + y) * HW + refl(tx0 - CEN + xx)];
        }
        __syncthreads();
        hconv4_d1<PIT, 24>(A, Y, 4, 11, tid);
    }
    __syncthreads();

    // W-conv 1: c1 -> A on rows 4..91 x cols 4..91; emit w1 = c0 - c1.
    if (interior)
        wconv<1, true, false, true, 22>(Y, A, 4, 88, 1, xb, ob, nullptr,
                                        ty0, tx0, tid);
    else
        wconv<1, true, false, false, 22>(Y, A, 4, 88, 1, nullptr, ob, nullptr,
                                         ty0, tx0, tid);
    __syncthreads();

    // Level 2 (d=2): h2 out rows 8..87 x cols 4..91.
    hconv2<2, 16, PIT, 44>(A, Y, 8, 5, 4, tid);
    __syncthreads();
    // w2: c2 -> A on rows 8..87 x cols 8..87; emit w2 = c1 - c2.
    wconv<2, true, false, false, 20>(Y, A, 8, 80, 2, nullptr,
                                     ob + (size_t)HW * HW, nullptr,
                                     ty0, tx0, tid);
    __syncthreads();

    // Level 3 (d=4): h3 out rows 16..79 x cols 8..87.
    hconv2<4, 16, PIT, 40>(A, Y, 16, 4, 8, tid);
    __syncthreads();
    // w3: center only; emit w3 = c2 - c3 and c3. No smem store.
    wconv<4, false, true, false, 16>(Y, A, 16, 64, 4, nullptr,
                                     ob + 2 * (size_t)HW * HW,
                                     ob + 3 * (size_t)HW * HW, ty0, tx0, tid);
}

extern "C" void kernel_launch(void* const* d_in, const int* in_sizes, int n_in,
                              void* d_out, int out_size) {
    const float* x = (const float*)d_in[0];
    float* out = (float*)d_out;
    const int smemBytes = 2 * Sg * PIT * (int)sizeof(float);  // 73728 B
    cudaFuncSetAttribute(uwt_kernel, cudaFuncAttributeMaxDynamicSharedMemorySize,
                         smemBytes);
    dim3 grid(256, 8);
    uwt_kernel<<<grid, NT, smemBytes>>>(x, out);
}